// round 2
// baseline (speedup 1.0000x reference)
#include <cuda_runtime.h>
#include <cuda_bf16.h>

#define SEQ   512
#define BATCH 64
#define EMB   512
#define HID   1024
#define NG    4096            // 4 gates * HID, layout n = hid*4 + gate (i,f,g,o)
#define MTOT  (SEQ*BATCH)     // 32768

// ---------------- device scratch (static: no allocations allowed) ----------------
__device__ __nv_bfloat16 g_Ehi[(size_t)MTOT * EMB];
__device__ __nv_bfloat16 g_Elo[(size_t)MTOT * EMB];
__device__ __nv_bfloat16 g_Wxhi[(size_t)NG * EMB];   // [n][k] (transposed for mma B)
__device__ __nv_bfloat16 g_Wxlo[(size_t)NG * EMB];
__device__ __nv_bfloat16 g_Whhi[(size_t)NG * HID];   // [n][k]
__device__ __nv_bfloat16 g_Whlo[(size_t)NG * HID];
__device__ float         g_bias[NG];
__device__ float         g_xproj[(size_t)MTOT * NG]; // 512 MB: x-projections, all t
__device__ float         g_c[BATCH * HID];
__device__ __nv_bfloat16 g_hhi[2][BATCH * HID];      // ping-pong h (hi/lo split)
__device__ __nv_bfloat16 g_hlo[2][BATCH * HID];

// ---------------- helpers ----------------
__device__ __forceinline__ void mma16816(float* d, const unsigned* a, const unsigned* b) {
    asm volatile(
        "mma.sync.aligned.m16n8k16.row.col.f32.bf16.bf16.f32 "
        "{%0,%1,%2,%3}, {%4,%5,%6,%7}, {%8,%9}, {%0,%1,%2,%3};\n"
        : "+f"(d[0]), "+f"(d[1]), "+f"(d[2]), "+f"(d[3])
        : "r"(a[0]), "r"(a[1]), "r"(a[2]), "r"(a[3]),
          "r"(b[0]), "r"(b[1]));
}

__device__ __forceinline__ void split2(float x, __nv_bfloat16& hi, __nv_bfloat16& lo) {
    hi = __float2bfloat16(x);
    lo = __float2bfloat16(x - __bfloat162float(hi));
}

// ---------------- conversion kernels ----------------
__global__ void k_conv_emb(const float* __restrict__ e) {
    int i = blockIdx.x * blockDim.x + threadIdx.x;
    if (i < MTOT * EMB) {
        __nv_bfloat16 h, l;
        split2(e[i], h, l);
        g_Ehi[i] = h; g_Elo[i] = l;
    }
}

__global__ void k_conv_wx(const float* __restrict__ Wi, const float* __restrict__ Wf,
                          const float* __restrict__ Wg, const float* __restrict__ Wo,
                          const float* __restrict__ bi, const float* __restrict__ bf_,
                          const float* __restrict__ bg, const float* __restrict__ bo) {
    int idx = blockIdx.x * blockDim.x + threadIdx.x;   // over NG*EMB
    if (idx >= NG * EMB) return;
    int n = idx >> 9;            // / EMB
    int k = idx & (EMB - 1);
    int gate = n & 3, hid = n >> 2;
    const float* W = (gate == 0) ? Wi : (gate == 1) ? Wf : (gate == 2) ? Wg : Wo;
    __nv_bfloat16 h, l;
    split2(W[(size_t)k * HID + hid], h, l);
    g_Wxhi[idx] = h; g_Wxlo[idx] = l;
    if (k == 0) {
        const float* b = (gate == 0) ? bi : (gate == 1) ? bf_ : (gate == 2) ? bg : bo;
        g_bias[n] = b[hid];
    }
}

__global__ void k_conv_wh(const float* __restrict__ Wi, const float* __restrict__ Wf,
                          const float* __restrict__ Wg, const float* __restrict__ Wo) {
    int idx = blockIdx.x * blockDim.x + threadIdx.x;   // over NG*HID
    if (idx >= NG * HID) return;
    int n = idx >> 10;           // / HID
    int k = idx & (HID - 1);
    int gate = n & 3, hid = n >> 2;
    const float* W = (gate == 0) ? Wi : (gate == 1) ? Wf : (gate == 2) ? Wg : Wo;
    __nv_bfloat16 h, l;
    split2(W[(size_t)k * HID + hid], h, l);
    g_Whhi[idx] = h; g_Whlo[idx] = l;
}

__global__ void k_init() {
    int i = blockIdx.x * blockDim.x + threadIdx.x;
    if (i < BATCH * HID) {
        g_c[i] = 0.f;
        g_hhi[0][i] = __float2bfloat16(0.f);
        g_hlo[0][i] = __float2bfloat16(0.f);
    }
}

// ---------------- phase 1: x-projection GEMM ----------------
// C[m][n] = sum_k E[m][k] * Wx_T[n][k] + bias[n], split-bf16 3-term.
// CTA tile 128x128, BK=32, 256 threads, warp tile 32(m) x 64(n).
__global__ __launch_bounds__(256) void k_xproj() {
    __shared__ __nv_bfloat16 sA[2][128][40];   // [hi/lo][m][k], pad 40 -> conflict free
    __shared__ __nv_bfloat16 sB[2][128][40];   // [hi/lo][n][k]
    const int tid = threadIdx.x;
    const int m0 = blockIdx.x * 128;
    const int n0 = blockIdx.y * 128;
    const int warp = tid >> 5, lane = tid & 31;
    const int g = lane >> 2, tq = lane & 3;
    const int wm = warp & 3, wn = warp >> 2;   // 4 m-warps x 2 n-warps

    float acc[2][8][4];
#pragma unroll
    for (int i = 0; i < 2; i++)
#pragma unroll
        for (int j = 0; j < 8; j++)
#pragma unroll
            for (int r = 0; r < 4; r++) acc[i][j][r] = 0.f;

    for (int kc = 0; kc < EMB; kc += 32) {
#pragma unroll
        for (int i = 0; i < 8; i++) {
            int idx = tid + i * 256;           // 2048 uint32 per operand tile
            int row = idx >> 4;
            int c2  = (idx & 15) << 1;
            size_t ga = (size_t)(m0 + row) * EMB + kc + c2;
            size_t gb = (size_t)(n0 + row) * EMB + kc + c2;
            *(unsigned*)&sA[0][row][c2] = *(const unsigned*)&g_Ehi[ga];
            *(unsigned*)&sA[1][row][c2] = *(const unsigned*)&g_Elo[ga];
            *(unsigned*)&sB[0][row][c2] = *(const unsigned*)&g_Wxhi[gb];
            *(unsigned*)&sB[1][row][c2] = *(const unsigned*)&g_Wxlo[gb];
        }
        __syncthreads();
#pragma unroll
        for (int kk = 0; kk < 32; kk += 16) {
            unsigned aHi[2][4], aLo[2][4];
#pragma unroll
            for (int im = 0; im < 2; im++) {
                int r = wm * 32 + im * 16 + g;
                int c = kk + tq * 2;
                aHi[im][0] = *(unsigned*)&sA[0][r][c];
                aHi[im][1] = *(unsigned*)&sA[0][r + 8][c];
                aHi[im][2] = *(unsigned*)&sA[0][r][c + 8];
                aHi[im][3] = *(unsigned*)&sA[0][r + 8][c + 8];
                aLo[im][0] = *(unsigned*)&sA[1][r][c];
                aLo[im][1] = *(unsigned*)&sA[1][r + 8][c];
                aLo[im][2] = *(unsigned*)&sA[1][r][c + 8];
                aLo[im][3] = *(unsigned*)&sA[1][r + 8][c + 8];
            }
#pragma unroll
            for (int j = 0; j < 8; j++) {
                int n = wn * 64 + j * 8 + g;
                int c = kk + tq * 2;
                unsigned bHi[2], bLo[2];
                bHi[0] = *(unsigned*)&sB[0][n][c];
                bHi[1] = *(unsigned*)&sB[0][n][c + 8];
                bLo[0] = *(unsigned*)&sB[1][n][c];
                bLo[1] = *(unsigned*)&sB[1][n][c + 8];
#pragma unroll
                for (int im = 0; im < 2; im++) {
                    mma16816(acc[im][j], aHi[im], bHi);
                    mma16816(acc[im][j], aHi[im], bLo);
                    mma16816(acc[im][j], aLo[im], bHi);
                }
            }
        }
        __syncthreads();
    }
#pragma unroll
    for (int im = 0; im < 2; im++)
#pragma unroll
        for (int j = 0; j < 8; j++)
#pragma unroll
            for (int r = 0; r < 4; r++) {
                int row = m0 + wm * 32 + im * 16 + g + ((r & 2) ? 8 : 0);
                int col = n0 + wn * 64 + j * 8 + tq * 2 + (r & 1);
                g_xproj[(size_t)row * NG + col] = acc[im][j][r] + g_bias[col];
            }
}

// ---------------- phase 2: one LSTM timestep ----------------
// gates[b][n] = xproj[t][b][n] + sum_k h[b][k] * Wh_T[n][k]  (split-bf16)
// CTA: M=64 (batch) x N=64 (16 hid x 4 gates), K=1024. 64 CTAs, 256 threads.
__global__ __launch_bounds__(256) void k_step(int t, float* __restrict__ out) {
    __shared__ __nv_bfloat16 sA[2][64][72];
    __shared__ __nv_bfloat16 sB[2][64][72];
    const int tid = threadIdx.x;
    const int n0 = blockIdx.x * 64;
    const int warp = tid >> 5, lane = tid & 31;
    const int g = lane >> 2, tq = lane & 3;
    const int wm = warp & 3, wn = warp >> 2;   // 4 m-warps (16 rows) x 2 n-warps (32 cols)
    const int slotR = t & 1, slotW = slotR ^ 1;
    const __nv_bfloat16* __restrict__ hHi = g_hhi[slotR];
    const __nv_bfloat16* __restrict__ hLo = g_hlo[slotR];

    float acc[4][4];
#pragma unroll
    for (int j = 0; j < 4; j++)
#pragma unroll
        for (int r = 0; r < 4; r++) acc[j][r] = 0.f;

    for (int kc = 0; kc < HID; kc += 64) {
#pragma unroll
        for (int i = 0; i < 8; i++) {
            int idx = tid + i * 256;           // 64 rows x 32 uints
            int row = idx >> 5;
            int c2  = (idx & 31) << 1;
            int ga = row * HID + kc + c2;
            size_t gb = (size_t)(n0 + row) * HID + kc + c2;
            *(unsigned*)&sA[0][row][c2] = *(const unsigned*)&hHi[ga];
            *(unsigned*)&sA[1][row][c2] = *(const unsigned*)&hLo[ga];
            *(unsigned*)&sB[0][row][c2] = *(const unsigned*)&g_Whhi[gb];
            *(unsigned*)&sB[1][row][c2] = *(const unsigned*)&g_Whlo[gb];
        }
        __syncthreads();
#pragma unroll
        for (int kk = 0; kk < 64; kk += 16) {
            unsigned aHi[4], aLo[4];
            int r = wm * 16 + g;
            int c = kk + tq * 2;
            aHi[0] = *(unsigned*)&sA[0][r][c];
            aHi[1] = *(unsigned*)&sA[0][r + 8][c];
            aHi[2] = *(unsigned*)&sA[0][r][c + 8];
            aHi[3] = *(unsigned*)&sA[0][r + 8][c + 8];
            aLo[0] = *(unsigned*)&sA[1][r][c];
            aLo[1] = *(unsigned*)&sA[1][r + 8][c];
            aLo[2] = *(unsigned*)&sA[1][r][c + 8];
            aLo[3] = *(unsigned*)&sA[1][r + 8][c + 8];
#pragma unroll
            for (int j = 0; j < 4; j++) {
                int n = wn * 32 + j * 8 + g;
                unsigned bHi[2], bLo[2];
                bHi[0] = *(unsigned*)&sB[0][n][c];
                bHi[1] = *(unsigned*)&sB[0][n][c + 8];
                bLo[0] = *(unsigned*)&sB[1][n][c];
                bLo[1] = *(unsigned*)&sB[1][n][c + 8];
                mma16816(acc[j], aHi, bHi);
                mma16816(acc[j], aHi, bLo);
                mma16816(acc[j], aLo, bHi);
            }
        }
        __syncthreads();
    }

    // gate pre-activations into smem (alias over sA; all reads of sA are done)
    float (*sG)[68] = (float(*)[68]) & sA[0][0][0];   // 64*68*4 = 17408 <= 18432
    const float* __restrict__ xp = &g_xproj[(size_t)t * BATCH * NG];
#pragma unroll
    for (int j = 0; j < 4; j++)
#pragma unroll
        for (int r = 0; r < 4; r++) {
            int row = wm * 16 + g + ((r & 2) ? 8 : 0);
            int col = wn * 32 + j * 8 + tq * 2 + (r & 1);
            sG[row][col] = acc[j][r] + xp[(size_t)row * NG + n0 + col];
        }
    __syncthreads();

    // pointwise LSTM cell: this CTA owns 16 hidden units x 64 batch
    for (int p = tid; p < BATCH * 16; p += 256) {
        int b = p >> 4, hh = p & 15;
        int hid = (n0 >> 2) + hh;
        float gi = sG[b][hh * 4 + 0];
        float gf = sG[b][hh * 4 + 1];
        float gg = sG[b][hh * 4 + 2];
        float go = sG[b][hh * 4 + 3];
        float iv = 1.f / (1.f + expf(-gi));
        float fv = 1.f / (1.f + expf(-gf));
        float ov = 1.f / (1.f + expf(-go));
        float gv = tanhf(gg);
        int ci = b * HID + hid;
        float cn = gv * iv + g_c[ci] * fv;
        float hv = tanhf(cn) * ov;
        g_c[ci] = cn;
        out[((size_t)t * BATCH + b) * HID + hid] = hv;
        __nv_bfloat16 hb, hl;
        split2(hv, hb, hl);
        g_hhi[slotW][ci] = hb;
        g_hlo[slotW][ci] = hl;
    }
}

// ---------------- launch ----------------
extern "C" void kernel_launch(void* const* d_in, const int* in_sizes, int n_in,
                              void* d_out, int out_size) {
    const float* embeds = (const float*)d_in[0];
    const float* W_ix = (const float*)d_in[1];
    const float* W_ih = (const float*)d_in[2];
    const float* b_i  = (const float*)d_in[3];
    const float* W_fx = (const float*)d_in[4];
    const float* W_fh = (const float*)d_in[5];
    const float* b_f  = (const float*)d_in[6];
    const float* W_gx = (const float*)d_in[7];
    const float* W_gh = (const float*)d_in[8];
    const float* b_g  = (const float*)d_in[9];
    const float* W_ox = (const float*)d_in[10];
    const float* W_oh = (const float*)d_in[11];
    const float* b_o  = (const float*)d_in[12];
    float* out = (float*)d_out;

    k_conv_emb<<<(MTOT * EMB + 255) / 256, 256>>>(embeds);
    k_conv_wx<<<(NG * EMB + 255) / 256, 256>>>(W_ix, W_fx, W_gx, W_ox, b_i, b_f, b_g, b_o);
    k_conv_wh<<<(NG * HID + 255) / 256, 256>>>(W_ih, W_fh, W_gh, W_oh);
    k_init<<<(BATCH * HID + 255) / 256, 256>>>();

    dim3 g1(MTOT / 128, NG / 128);   // (256, 32)
    k_xproj<<<g1, 256>>>();

    for (int t = 0; t < SEQ; t++)
        k_step<<<NG / 64, 256>>>(t, out);
}

// round 9
// speedup vs baseline: 2.6093x; 2.6093x over previous
#include <cuda_runtime.h>
#include <cuda_bf16.h>

#define SEQ   512
#define BATCH 64
#define EMB   512
#define HID   1024
#define NG    4096            // 4 gates * HID, layout n = hid*4 + gate (i,f,g,o)
#define MTOT  (SEQ*BATCH)     // 32768
#define NCTA  128             // persistent recurrence CTAs (1/SM, co-resident)

// ---------------- device scratch (static: no allocations allowed) ----------------
__device__ __nv_bfloat16 g_Ehi[(size_t)MTOT * EMB];
__device__ __nv_bfloat16 g_Elo[(size_t)MTOT * EMB];
__device__ __nv_bfloat16 g_Wxhi[(size_t)NG * EMB];   // [n][k] (transposed for mma B)
__device__ __nv_bfloat16 g_Wxlo[(size_t)NG * EMB];
__device__ __nv_bfloat16 g_Whhi[(size_t)NG * HID];   // [n][k]
__device__ __nv_bfloat16 g_Whlo[(size_t)NG * HID];
__device__ float         g_bias[NG];
__device__ float         g_xproj[(size_t)MTOT * NG]; // 512 MB: x-projections, all t
__device__ __nv_bfloat16 g_hhi[2][BATCH * HID];      // ping-pong h (hi/lo split)
__device__ __nv_bfloat16 g_hlo[2][BATCH * HID];
__device__ int           g_arrive;                   // global barrier epoch counter

// ---------------- helpers ----------------
__device__ __forceinline__ void mma16816(float* d, const unsigned* a, const unsigned* b) {
    asm volatile(
        "mma.sync.aligned.m16n8k16.row.col.f32.bf16.bf16.f32 "
        "{%0,%1,%2,%3}, {%4,%5,%6,%7}, {%8,%9}, {%0,%1,%2,%3};\n"
        : "+f"(d[0]), "+f"(d[1]), "+f"(d[2]), "+f"(d[3])
        : "r"(a[0]), "r"(a[1]), "r"(a[2]), "r"(a[3]),
          "r"(b[0]), "r"(b[1]));
}

__device__ __forceinline__ void split2(float x, __nv_bfloat16& hi, __nv_bfloat16& lo) {
    hi = __float2bfloat16(x);
    lo = __float2bfloat16(x - __bfloat162float(hi));
}

__device__ __forceinline__ void cp16(unsigned smem_dst, const void* gsrc) {
    asm volatile("cp.async.cg.shared.global [%0], [%1], 16;\n" :: "r"(smem_dst), "l"(gsrc));
}
__device__ __forceinline__ void cp_commit() { asm volatile("cp.async.commit_group;\n"); }
template <int N>
__device__ __forceinline__ void cp_wait() { asm volatile("cp.async.wait_group %0;\n" :: "n"(N)); }

// ---------------- conversion kernels ----------------
__global__ void k_conv_emb(const float* __restrict__ e) {
    int i = blockIdx.x * blockDim.x + threadIdx.x;
    if (i < MTOT * EMB) {
        __nv_bfloat16 h, l;
        split2(e[i], h, l);
        g_Ehi[i] = h; g_Elo[i] = l;
    }
}

__global__ void k_conv_wx(const float* __restrict__ Wi, const float* __restrict__ Wf,
                          const float* __restrict__ Wg, const float* __restrict__ Wo,
                          const float* __restrict__ bi, const float* __restrict__ bf_,
                          const float* __restrict__ bg, const float* __restrict__ bo) {
    int idx = blockIdx.x * blockDim.x + threadIdx.x;   // over NG*EMB
    if (idx >= NG * EMB) return;
    int n = idx >> 9;            // / EMB
    int k = idx & (EMB - 1);
    int gate = n & 3, hid = n >> 2;
    const float* W = (gate == 0) ? Wi : (gate == 1) ? Wf : (gate == 2) ? Wg : Wo;
    __nv_bfloat16 h, l;
    split2(W[(size_t)k * HID + hid], h, l);
    g_Wxhi[idx] = h; g_Wxlo[idx] = l;
    if (k == 0) {
        const float* b = (gate == 0) ? bi : (gate == 1) ? bf_ : (gate == 2) ? bg : bo;
        g_bias[n] = b[hid];
    }
}

__global__ void k_conv_wh(const float* __restrict__ Wi, const float* __restrict__ Wf,
                          const float* __restrict__ Wg, const float* __restrict__ Wo) {
    int idx = blockIdx.x * blockDim.x + threadIdx.x;   // over NG*HID
    if (idx >= NG * HID) return;
    int n = idx >> 10;           // / HID
    int k = idx & (HID - 1);
    int gate = n & 3, hid = n >> 2;
    const float* W = (gate == 0) ? Wi : (gate == 1) ? Wf : (gate == 2) ? Wg : Wo;
    __nv_bfloat16 h, l;
    split2(W[(size_t)k * HID + hid], h, l);
    g_Whhi[idx] = h; g_Whlo[idx] = l;
}

__global__ void k_init() {
    int i = blockIdx.x * blockDim.x + threadIdx.x;
    if (i == 0) g_arrive = 0;
    if (i < BATCH * HID) {
        g_hhi[0][i] = __float2bfloat16(0.f);
        g_hlo[0][i] = __float2bfloat16(0.f);
    }
}

// ---------------- phase 1: x-projection GEMM ----------------
// C[m][n] = sum_k E[m][k] * Wx_T[n][k] + bias[n], split-bf16 3-term.
// CTA tile 128x128, BK=32, 256 threads, warp tile 32(m) x 64(n).
__global__ __launch_bounds__(256) void k_xproj() {
    __shared__ __nv_bfloat16 sA[2][128][40];
    __shared__ __nv_bfloat16 sB[2][128][40];
    const int tid = threadIdx.x;
    const int m0 = blockIdx.x * 128;
    const int n0 = blockIdx.y * 128;
    const int warp = tid >> 5, lane = tid & 31;
    const int g = lane >> 2, tq = lane & 3;
    const int wm = warp & 3, wn = warp >> 2;

    float acc[2][8][4];
#pragma unroll
    for (int i = 0; i < 2; i++)
#pragma unroll
        for (int j = 0; j < 8; j++)
#pragma unroll
            for (int r = 0; r < 4; r++) acc[i][j][r] = 0.f;

    for (int kc = 0; kc < EMB; kc += 32) {
#pragma unroll
        for (int i = 0; i < 8; i++) {
            int idx = tid + i * 256;
            int row = idx >> 4;
            int c2  = (idx & 15) << 1;
            size_t ga = (size_t)(m0 + row) * EMB + kc + c2;
            size_t gb = (size_t)(n0 + row) * EMB + kc + c2;
            *(unsigned*)&sA[0][row][c2] = *(const unsigned*)&g_Ehi[ga];
            *(unsigned*)&sA[1][row][c2] = *(const unsigned*)&g_Elo[ga];
            *(unsigned*)&sB[0][row][c2] = *(const unsigned*)&g_Wxhi[gb];
            *(unsigned*)&sB[1][row][c2] = *(const unsigned*)&g_Wxlo[gb];
        }
        __syncthreads();
#pragma unroll
        for (int kk = 0; kk < 32; kk += 16) {
            unsigned aHi[2][4], aLo[2][4];
#pragma unroll
            for (int im = 0; im < 2; im++) {
                int r = wm * 32 + im * 16 + g;
                int c = kk + tq * 2;
                aHi[im][0] = *(unsigned*)&sA[0][r][c];
                aHi[im][1] = *(unsigned*)&sA[0][r + 8][c];
                aHi[im][2] = *(unsigned*)&sA[0][r][c + 8];
                aHi[im][3] = *(unsigned*)&sA[0][r + 8][c + 8];
                aLo[im][0] = *(unsigned*)&sA[1][r][c];
                aLo[im][1] = *(unsigned*)&sA[1][r + 8][c];
                aLo[im][2] = *(unsigned*)&sA[1][r][c + 8];
                aLo[im][3] = *(unsigned*)&sA[1][r + 8][c + 8];
            }
#pragma unroll
            for (int j = 0; j < 8; j++) {
                int n = wn * 64 + j * 8 + g;
                int c = kk + tq * 2;
                unsigned bHi[2], bLo[2];
                bHi[0] = *(unsigned*)&sB[0][n][c];
                bHi[1] = *(unsigned*)&sB[0][n][c + 8];
                bLo[0] = *(unsigned*)&sB[1][n][c];
                bLo[1] = *(unsigned*)&sB[1][n][c + 8];
#pragma unroll
                for (int im = 0; im < 2; im++) {
                    mma16816(acc[im][j], aHi[im], bHi);
                    mma16816(acc[im][j], aHi[im], bLo);
                    mma16816(acc[im][j], aLo[im], bHi);
                }
            }
        }
        __syncthreads();
    }
#pragma unroll
    for (int im = 0; im < 2; im++)
#pragma unroll
        for (int j = 0; j < 8; j++)
#pragma unroll
            for (int r = 0; r < 4; r++) {
                int row = m0 + wm * 32 + im * 16 + g + ((r & 2) ? 8 : 0);
                int col = n0 + wn * 64 + j * 8 + tq * 2 + (r & 1);
                g_xproj[(size_t)row * NG + col] = acc[im][j][r] + g_bias[col];
            }
}

// ---------------- phase 2: persistent recurrence kernel ----------------
// 128 CTAs x 256 threads, 1 CTA/SM (smem-forced). CTA bx owns gate-cols
// [bx*32, bx*32+32) == hidden units [bx*8, bx*8+8).
// Smem: sW [hl][32][1032] bf16 (weights, resident all steps) = 132096 B
//       sA [slot][hl][64][136] bf16 (h chunks, double buffered) =  69632 B
//       sRed/sG alias the sA region after the MMA loop.
// Warp layout: 8 warps = 4 m-warps (16 rows) x 2 k-groups. Per step each
// warp computes m16 x n32 over its K=512 half, then k-pair smem reduce.
#define SW_ELEMS  (2 * 32 * 1032)
#define SW_BYTES  (SW_ELEMS * 2)          // 132096
#define SA_ROWP   136
#define SA_BYTES  (2 * 2 * 64 * SA_ROWP * 2)  // 69632
#define SMEM_TOT  (SW_BYTES + SA_BYTES)   // 201728

__global__ __launch_bounds__(256, 1) void k_recur(float* __restrict__ out) {
    extern __shared__ char smem[];
    __nv_bfloat16* sW = (__nv_bfloat16*)smem;                 // [hl*32+n][1032]
    __nv_bfloat16* sA = (__nv_bfloat16*)(smem + SW_BYTES);    // [(slot*2+hl)*64+row][136]
    float* sRed = (float*)(smem + SW_BYTES);                  // alias, 8 KB
    float* sG   = (float*)(smem + SW_BYTES + 8192);           // [64][33] fp32

    const int tid = threadIdx.x;
    const int bx = blockIdx.x;
    const int n0 = bx * 32;
    const int warp = tid >> 5, lane = tid & 31;
    const int g = lane >> 2, tq = lane & 3;
    const int wm = warp & 3, wk = warp >> 2;
    const unsigned sAaddr = (unsigned)__cvta_generic_to_shared(sA);
    const unsigned sWaddr = (unsigned)__cvta_generic_to_shared(sW);

    // ---- preload this CTA's Wh slice (hi+lo, 128 KB) into smem ----
#pragma unroll
    for (int i = 0; i < 32; i++) {
        int idx = tid + i * 256;          // 0..8191
        int row = idx >> 7;               // hl*32 + n
        int seg = idx & 127;
        int hl = row >> 5, n = row & 31;
        const __nv_bfloat16* src = (hl ? g_Whlo : g_Whhi) + (size_t)(n0 + n) * HID + seg * 8;
        cp16(sWaddr + row * 2064 + seg * 16, src);
    }
    cp_commit();
    cp_wait<0>();
    __syncthreads();

    // cell state lives in registers: thread -> (batch pb, units pu0, pu0+1)
    const int pb  = tid >> 2;
    const int pu0 = (tid & 3) * 2;
    float cc0 = 0.f, cc1 = 0.f;

    for (int t = 0; t < SEQ; t++) {
        const int slotR = t & 1, slotW = slotR ^ 1;
        const __nv_bfloat16* __restrict__ hHi = g_hhi[slotR];
        const __nv_bfloat16* __restrict__ hLo = g_hlo[slotR];

        // prefetch xproj for the epilogue (wk==0 warps only; hides DRAM latency)
        float xpr[4][4];
        if (wk == 0) {
            const float* xp = g_xproj + ((size_t)t * BATCH) * NG + n0;
#pragma unroll
            for (int j = 0; j < 4; j++)
#pragma unroll
                for (int r = 0; r < 4; r++) {
                    int row = wm * 16 + g + ((r & 2) ? 8 : 0);
                    int col = j * 8 + tq * 2 + (r & 1);
                    xpr[j][r] = xp[(size_t)row * NG + col];
                }
        }

        float acc[4][4];
#pragma unroll
        for (int j = 0; j < 4; j++)
#pragma unroll
            for (int r = 0; r < 4; r++) acc[j][r] = 0.f;

        // ---- pipelined chunk loop: 8 chunks of K=128, double buffered ----
        // chunk load: 2048 cp16 (hi+lo), 8 per thread
#define LOAD_CHUNK(C, SLOT)                                                        \
        {                                                                          \
            _Pragma("unroll")                                                      \
            for (int i = 0; i < 8; i++) {                                          \
                int idx = tid + i * 256;                                           \
                int hl = idx >> 10;                                                \
                int r  = (idx >> 4) & 63;                                          \
                int seg = idx & 15;                                                \
                const __nv_bfloat16* src = (hl ? hLo : hHi) + r * HID + (C) * 128 + seg * 8; \
                cp16(sAaddr + (((SLOT) * 2 + hl) * 64 + r) * (SA_ROWP * 2) + seg * 16, src); \
            }                                                                      \
        }

        LOAD_CHUNK(0, 0);
        cp_commit();
#pragma unroll 1
        for (int c = 0; c < 8; c++) {
            if (c < 7) {
                LOAD_CHUNK(c + 1, (c + 1) & 1);
                cp_commit();
                cp_wait<1>();
            } else {
                cp_wait<0>();
            }
            __syncthreads();
            const int slot = c & 1;
#pragma unroll
            for (int kk = 0; kk < 4; kk++) {
                int lc = wk * 64 + kk * 16 + tq * 2;   // local col in chunk
                int gc = c * 128 + lc;                 // global k col in sW
                int r0 = wm * 16 + g;
                unsigned aHi[4], aLo[4];
                aHi[0] = *(unsigned*)&sA[((slot * 2 + 0) * 64 + r0) * SA_ROWP + lc];
                aHi[1] = *(unsigned*)&sA[((slot * 2 + 0) * 64 + r0 + 8) * SA_ROWP + lc];
                aHi[2] = *(unsigned*)&sA[((slot * 2 + 0) * 64 + r0) * SA_ROWP + lc + 8];
                aHi[3] = *(unsigned*)&sA[((slot * 2 + 0) * 64 + r0 + 8) * SA_ROWP + lc + 8];
                aLo[0] = *(unsigned*)&sA[((slot * 2 + 1) * 64 + r0) * SA_ROWP + lc];
                aLo[1] = *(unsigned*)&sA[((slot * 2 + 1) * 64 + r0 + 8) * SA_ROWP + lc];
                aLo[2] = *(unsigned*)&sA[((slot * 2 + 1) * 64 + r0) * SA_ROWP + lc + 8];
                aLo[3] = *(unsigned*)&sA[((slot * 2 + 1) * 64 + r0 + 8) * SA_ROWP + lc + 8];
#pragma unroll
                for (int j = 0; j < 4; j++) {
                    int n = j * 8 + g;
                    unsigned bHi[2], bLo[2];
                    bHi[0] = *(unsigned*)&sW[(n) * 1032 + gc];
                    bHi[1] = *(unsigned*)&sW[(n) * 1032 + gc + 8];
                    bLo[0] = *(unsigned*)&sW[(32 + n) * 1032 + gc];
                    bLo[1] = *(unsigned*)&sW[(32 + n) * 1032 + gc + 8];
                    mma16816(acc[j], aHi, bHi);
                    mma16816(acc[j], aHi, bLo);
                    mma16816(acc[j], aLo, bHi);
                }
            }
            __syncthreads();
        }

        // ---- reduce k-pairs (wk=1 -> smem -> wk=0 adds) ----
        if (wk == 1) {
            float* dst = &sRed[(wm * 32 + lane) * 16];
#pragma unroll
            for (int j = 0; j < 4; j++)
#pragma unroll
                for (int r = 0; r < 4; r++) dst[j * 4 + r] = acc[j][r];
        }
        __syncthreads();
        if (wk == 0) {
            const float* srcr = &sRed[(wm * 32 + lane) * 16];
#pragma unroll
            for (int j = 0; j < 4; j++)
#pragma unroll
                for (int r = 0; r < 4; r++) {
                    float v = acc[j][r] + srcr[j * 4 + r] + xpr[j][r];
                    int row = wm * 16 + g + ((r & 2) ? 8 : 0);
                    int col = j * 8 + tq * 2 + (r & 1);
                    sG[row * 33 + col] = v;
                }
        }
        __syncthreads();

        // ---- pointwise LSTM cell (c in registers) ----
#pragma unroll
        for (int uu = 0; uu < 2; uu++) {
            int u = pu0 + uu;
            float gi = sG[pb * 33 + u * 4 + 0];
            float gf = sG[pb * 33 + u * 4 + 1];
            float gg = sG[pb * 33 + u * 4 + 2];
            float go = sG[pb * 33 + u * 4 + 3];
            float iv = 1.f / (1.f + __expf(-gi));
            float fv = 1.f / (1.f + __expf(-gf));
            float ov = 1.f / (1.f + __expf(-go));
            float gv = tanhf(gg);
            float cprev = uu ? cc1 : cc0;
            float cn = gv * iv + cprev * fv;
            if (uu) cc1 = cn; else cc0 = cn;
            float hv = tanhf(cn) * ov;
            int hid = bx * 8 + u;
            out[((size_t)t * BATCH + pb) * HID + hid] = hv;
            __nv_bfloat16 hb, hl2;
            split2(hv, hb, hl2);
            g_hhi[slotW][pb * HID + hid] = hb;
            g_hlo[slotW][pb * HID + hid] = hl2;
        }

        // ---- grid-wide barrier (epoch counter; all 128 CTAs co-resident) ----
        __threadfence();
        __syncthreads();
        if (tid == 0) {
            atomicAdd(&g_arrive, 1);
            int target = NCTA * (t + 1);
            while (((volatile int*)&g_arrive)[0] < target) {
                __nanosleep(64);   // back off: avoid 128-way L2 line hammering
            }
            __threadfence();       // acquire side: order subsequent h reads after spin
        }
        __syncthreads();
    }
#undef LOAD_CHUNK
}

// ---------------- launch ----------------
extern "C" void kernel_launch(void* const* d_in, const int* in_sizes, int n_in,
                              void* d_out, int out_size) {
    const float* embeds = (const float*)d_in[0];
    const float* W_ix = (const float*)d_in[1];
    const float* W_ih = (const float*)d_in[2];
    const float* b_i  = (const float*)d_in[3];
    const float* W_fx = (const float*)d_in[4];
    const float* W_fh = (const float*)d_in[5];
    const float* b_f  = (const float*)d_in[6];
    const float* W_gx = (const float*)d_in[7];
    const float* W_gh = (const float*)d_in[8];
    const float* b_g  = (const float*)d_in[9];
    const float* W_ox = (const float*)d_in[10];
    const float* W_oh = (const float*)d_in[11];
    const float* b_o  = (const float*)d_in[12];
    float* out = (float*)d_out;

    cudaFuncSetAttribute(k_recur, cudaFuncAttributeMaxDynamicSharedMemorySize, SMEM_TOT);

    k_conv_emb<<<(MTOT * EMB + 255) / 256, 256>>>(embeds);
    k_conv_wx<<<(NG * EMB + 255) / 256, 256>>>(W_ix, W_fx, W_gx, W_ox, b_i, b_f, b_g, b_o);
    k_conv_wh<<<(NG * HID + 255) / 256, 256>>>(W_ih, W_fh, W_gh, W_oh);
    k_init<<<(BATCH * HID + 255) / 256, 256>>>();

    dim3 g1(MTOT / 128, NG / 128);   // (256, 32)
    k_xproj<<<g1, 256>>>();

    k_recur<<<NCTA, 256, SMEM_TOT>>>(out);
}